// round 12
// baseline (speedup 1.0000x reference)
#include <cuda_runtime.h>

#define NBATCH   32768
#define WARPS    8
#define NTHREADS 256
#define IMGS     2
#define GRIDB    444                     // 148 SMs x 3 resident blocks
#define NGROUPS  (NBATCH / IMGS)         // 16384
#define WSTRIDE  (GRIDB * WARPS)         // 3552 warps

// ---- weight region offsets (floats) ----
#define OFF_WT   0        // patch-embed weights, cc-major k: WT[c][k'] stride 52, k'=cc*7+rr, pad 49..51
#define OFF_BMAP 1440
#define OFF_LNG  1464
#define OFF_LNB  1496
#define OFF_WQ   1528     // 4 heads x 72
#define OFF_WK   1816
#define OFF_WV   2104
#define OFF_WO   2392
#define OFF_BQ   2680
#define OFF_BK   2712
#define OFF_BV   2744
#define OFF_BO   2776
#define OFF_W1T  2808     // W1 transposed: 32 x 36
#define OFF_B1   3960
#define OFF_W2T  3992     // 32 x 36
#define OFF_B2   5144
#define OFF_WC1T 5176     // 64 x 36
#define OFF_BC1  7480
#define OFF_WC2T 7544     // 10 x 68
#define OFF_BC2  8224
#define WEIGHT_FLOATS 8240

// ---- per-warp scratch (floats) ----
#define SC_PIX 0          // 856 floats; dead after phase B
#define SC_H   0          // 16 x 32 quad-rotated (overlays PIX)
#define SC_Y1  0          // 2 x 32 (row phases reuse dead PIX)
#define SC_ENC 64         // 2 x 32
#define SC_C1B 128        // 2 x 64
#define SC_ROW 960        // 32: oe scratch
#define SC_X0  992        // 32
#define SC_H2B 1024       // 2 x 32 batched h2 (must NOT overlap PIX)
#define SCRATCH_PER_WARP 1088

#define SMEM_FLOATS (WEIGHT_FLOATS + WARPS * SCRATCH_PER_WARP)   // 16944
#define SMEM_BYTES  (SMEM_FLOATS * 4)                            // 67776 B -> 3 blocks/SM

typedef unsigned long long ull;

__device__ __forceinline__ ull pk2(float lo, float hi) {
    ull r; asm("mov.b64 %0, {%1, %2};" : "=l"(r) : "f"(lo), "f"(hi)); return r;
}
__device__ __forceinline__ void up2(float& lo, float& hi, ull v) {
    asm("mov.b64 {%0, %1}, %2;" : "=f"(lo), "=f"(hi) : "l"(v));
}
__device__ __forceinline__ void ffma2(ull& acc, ull a, ull b) {
    asm("fma.rn.f32x2 %0, %1, %2, %0;" : "+l"(acc) : "l"(a), "l"(b));
}

__device__ __forceinline__ float warp_ln32(float v, float gg, float bb) {
    float s1 = v, s2 = v * v;
    #pragma unroll
    for (int o = 16; o; o >>= 1) {
        s1 += __shfl_xor_sync(0xffffffffu, s1, o);
        s2 += __shfl_xor_sync(0xffffffffu, s2, o);
    }
    float mu  = s1 * 0.03125f;
    float var = fmaf(s2, 0.03125f, -mu * mu);
    float rstd = rsqrtf(var + 1e-5f);
    return (v - mu) * rstd * gg + bb;
}

// h layout: h[t][c] at t*32 + (((c>>2) + 2*(t>>2)) & 7)*4 + (c&3)
__device__ __forceinline__ int haddr(int t, int c) {
    return t * 32 + (((((c >> 2) + ((t >> 2) << 1)) & 7)) << 2) + (c & 3);
}

__global__ __launch_bounds__(NTHREADS, 3)
void vit_kernel(const float* __restrict__ img,
                const float* __restrict__ W_map, const float* __restrict__ b_map,
                const float* __restrict__ ln_g,  const float* __restrict__ ln_b,
                const float* __restrict__ Wq, const float* __restrict__ bq,
                const float* __restrict__ Wk, const float* __restrict__ bk,
                const float* __restrict__ Wv, const float* __restrict__ bv,
                const float* __restrict__ Wo, const float* __restrict__ bo,
                const float* __restrict__ W1, const float* __restrict__ b1,
                const float* __restrict__ W2, const float* __restrict__ b2,
                const float* __restrict__ Wc1, const float* __restrict__ bc1,
                const float* __restrict__ Wc2, const float* __restrict__ bc2,
                float* __restrict__ out)
{
    extern __shared__ float sm[];
    const int tid = threadIdx.x;

    // ---- cooperative weight staging: ONCE per block ----
    for (int i = tid; i < 1248; i += NTHREADS) {
        int c = i / 52, k = i - c * 52;
        float v = 0.0f;
        if (k < 49) {
            int cc = k / 7, rr = k - cc * 7;
            v = W_map[(rr * 7 + cc) * 24 + c];
        }
        sm[OFF_WT + i] = v;
    }
    for (int i = tid; i < 24; i += NTHREADS) sm[OFF_BMAP + i] = b_map[i];
    for (int i = tid; i < 32; i += NTHREADS) {
        sm[OFF_LNG + i] = ln_g[i]; sm[OFF_LNB + i] = ln_b[i];
        sm[OFF_BQ  + i] = bq[i];   sm[OFF_BK  + i] = bk[i];
        sm[OFF_BV  + i] = bv[i];   sm[OFF_BO  + i] = bo[i];
        sm[OFF_B1  + i] = b1[i];   sm[OFF_B2  + i] = b2[i];
    }
    for (int i = tid; i < 256; i += NTHREADS) {
        int h = i >> 6, r = i & 63;
        sm[OFF_WQ + h * 72 + r] = Wq[i];
        sm[OFF_WK + h * 72 + r] = Wk[i];
        sm[OFF_WV + h * 72 + r] = Wv[i];
        sm[OFF_WO + h * 72 + r] = Wo[i];
    }
    for (int i = tid; i < 1152; i += NTHREADS) {
        int col = i / 36, d = i - col * 36;
        sm[OFF_W1T + i] = (d < 32) ? W1[d * 32 + col] : 0.0f;
        sm[OFF_W2T + i] = (d < 32) ? W2[d * 32 + col] : 0.0f;
    }
    for (int i = tid; i < 2304; i += NTHREADS) {
        int o = i / 36, d = i - o * 36;
        sm[OFF_WC1T + i] = (d < 32) ? Wc1[d * 64 + o] : 0.0f;
    }
    for (int i = tid; i < 64; i += NTHREADS) sm[OFF_BC1 + i] = bc1[i];
    for (int i = tid; i < 680; i += NTHREADS) {
        int o = i / 68, m = i - o * 68;
        sm[OFF_WC2T + i] = (m < 64) ? Wc2[m * 10 + o] : 0.0f;
    }
    for (int i = tid; i < 16; i += NTHREADS) sm[OFF_BC2 + i] = (i < 10) ? bc2[i] : 0.0f;
    __syncthreads();

    const int warp = tid >> 5, lane = tid & 31;
    float* sc = sm + WEIGHT_FLOATS + warp * SCRATCH_PER_WARP;
    const int grp = lane >> 3, colgrp = lane & 7;
    const int hh = lane >> 3, ee = lane & 7;
    const int gwarp = blockIdx.x * WARPS + warp;

    // ---- block-lifetime register-resident constants ----
    const float gg = sm[OFF_LNG + lane], bb = sm[OFF_LNB + lane];
    float wkr[8], wvr[8];
    {
        const float* WkS = sm + OFF_WK + hh * 72 + ee;
        const float* WvS = sm + OFF_WV + hh * 72 + ee;
        #pragma unroll
        for (int e = 0; e < 8; e++) { wkr[e] = WkS[e * 8]; wvr[e] = WvS[e * 8]; }
    }
    const float bkr = sm[OFF_BK + lane], bvr = sm[OFF_BV + lane];
    const float bqr = sm[OFF_BQ + lane];

    // ---- persistent warp loop over image pairs ----
    #pragma unroll 1
    for (int g = gwarp; g < NGROUPS; g += WSTRIDE) {
        const int imgBase = g * IMGS;
        float mh_arr[IMGS];

        #pragma unroll 1
        for (int it = 0; it < IMGS; ++it) {
            const int imgIdx = imgBase + it;

            // ---- Phase A: load image -> token-minor pixel layout ----
            {
                const float4* gim4 = (const float4*)(img + (size_t)imgIdx * 784);
                #pragma unroll
                for (int k2 = 0; k2 < 7; k2++) {
                    int i4 = lane + k2 * 32;
                    if (i4 < 196) {
                        float4 v = gim4[i4];
                        float vals[4] = {v.x, v.y, v.z, v.w};
                        int p0 = i4 * 4;
                        #pragma unroll
                        for (int b = 0; b < 4; b++) {
                            int p = p0 + b;
                            int row = p / 28, col = p - row * 28;
                            int pr = row / 7, rr = row - pr * 7;
                            int pc = col / 7, cc = col - pc * 7;
                            sc[SC_PIX + pr * 216 + (cc * 7 + rr) * 4 + pc] = vals[b];
                        }
                    }
                }
                #pragma unroll
                for (int m = 0; m < 2; m++) {
                    int idx = lane + m * 32;
                    if (idx < 48) {
                        int t = idx / 3, kp = 49 + idx - (idx / 3) * 3;
                        sc[SC_PIX + (t >> 2) * 216 + kp * 4 + (t & 3)] = 0.0f;
                    }
                }
            }
            __syncwarp();

            // ---- Phase B: patch embedding, packed f32x2 ----
            float acc[4][3];
            {
                const float* pixbase = sc + SC_PIX + grp * 216;
                const float* wt = sm + OFF_WT + colgrp * 156;
                ull accp[3][2];
                #pragma unroll
                for (int c = 0; c < 3; c++) {
                    float bm = sm[OFF_BMAP + colgrp * 3 + c];
                    accp[c][0] = pk2(bm, bm);
                    accp[c][1] = accp[c][0];
                }
                #pragma unroll
                for (int k4 = 0; k4 < 13; k4++) {
                    ulonglong2 pv0 = *(const ulonglong2*)(pixbase + (k4 * 4 + 0) * 4);
                    ulonglong2 pv1 = *(const ulonglong2*)(pixbase + (k4 * 4 + 1) * 4);
                    ulonglong2 pv2 = *(const ulonglong2*)(pixbase + (k4 * 4 + 2) * 4);
                    ulonglong2 pv3 = *(const ulonglong2*)(pixbase + (k4 * 4 + 3) * 4);
                    #pragma unroll
                    for (int c = 0; c < 3; c++) {
                        float4 w = *(const float4*)(wt + c * 52 + k4 * 4);
                        ull w0 = pk2(w.x, w.x), w1 = pk2(w.y, w.y);
                        ull w2 = pk2(w.z, w.z), w3 = pk2(w.w, w.w);
                        ffma2(accp[c][0], pv0.x, w0); ffma2(accp[c][1], pv0.y, w0);
                        ffma2(accp[c][0], pv1.x, w1); ffma2(accp[c][1], pv1.y, w1);
                        ffma2(accp[c][0], pv2.x, w2); ffma2(accp[c][1], pv2.y, w2);
                        ffma2(accp[c][0], pv3.x, w3); ffma2(accp[c][1], pv3.y, w3);
                    }
                }
                #pragma unroll
                for (int c = 0; c < 3; c++) {
                    up2(acc[0][c], acc[1][c], accp[c][0]);
                    up2(acc[2][c], acc[3][c], accp[c][1]);
                }
            }
            __syncwarp();     // everyone done reading PIX before H overlays it

            // ---- Phase C: LayerNorm 1 on register tile; H overlays PIX ----
            {
                const int c0 = 8 + colgrp * 3;
                const float g0 = sm[OFF_LNG + c0],     b0 = sm[OFF_LNB + c0];
                const float g1 = sm[OFF_LNG + c0 + 1], b1v = sm[OFF_LNB + c0 + 1];
                const float g2 = sm[OFF_LNG + c0 + 2], b2v = sm[OFF_LNB + c0 + 2];
                const float gp = sm[OFF_LNG + colgrp], bp = sm[OFF_LNB + colgrp];
                #pragma unroll
                for (int j = 0; j < 4; j++) {
                    float a0 = acc[j][0], a1 = acc[j][1], a2 = acc[j][2];
                    float s1 = a0 + a1 + a2;
                    float s2 = fmaf(a0, a0, fmaf(a1, a1, a2 * a2));
                    #pragma unroll
                    for (int o = 1; o < 8; o <<= 1) {
                        s1 += __shfl_xor_sync(0xffffffffu, s1, o);
                        s2 += __shfl_xor_sync(0xffffffffu, s2, o);
                    }
                    float mu = s1 * 0.03125f;
                    float var = fmaf(s2, 0.03125f, -mu * mu);
                    float rstd = rsqrtf(var + 1e-5f);
                    int t = grp * 4 + j;
                    sc[SC_H + haddr(t, colgrp)] = fmaf(-mu * rstd, gp, bp);
                    sc[SC_H + haddr(t, c0    )] = fmaf((a0 - mu) * rstd, g0, b0);
                    sc[SC_H + haddr(t, c0 + 1)] = fmaf((a1 - mu) * rstd, g1, b1v);
                    sc[SC_H + haddr(t, c0 + 2)] = fmaf((a2 - mu) * rstd, g2, b2v);
                }
                if (grp == 0) {
                    sc[SC_X0 + c0] = acc[0][0]; sc[SC_X0 + c0 + 1] = acc[0][1]; sc[SC_X0 + c0 + 2] = acc[0][2];
                }
                if (lane < 8) sc[SC_X0 + lane] = 0.0f;
            }
            __syncwarp();

            // ---- Phase D+E fused: q0 peel, then online-softmax attention ----
            float oe;
            {
                float q0;
                {
                    const float* WqS = sm + OFF_WQ + hh * 72 + ee;
                    const float* hb = sc + SC_H;
                    float4 h0 = *(const float4*)(hb + (((2 * hh) & 7) << 2));
                    float4 h1 = *(const float4*)(hb + (((2 * hh + 1) & 7) << 2));
                    float aq = bqr;
                    aq = fmaf(h0.x, WqS[0],  aq); aq = fmaf(h0.y, WqS[8],  aq);
                    aq = fmaf(h0.z, WqS[16], aq); aq = fmaf(h0.w, WqS[24], aq);
                    aq = fmaf(h1.x, WqS[32], aq); aq = fmaf(h1.y, WqS[40], aq);
                    aq = fmaf(h1.z, WqS[48], aq); aq = fmaf(h1.w, WqS[56], aq);
                    q0 = aq * 0.35355339059327373f;   // fold 1/sqrt(8)
                }
                float ssum = 0.0f, oacc = 0.0f;
                #pragma unroll
                for (int s = 0; s < 16; s++) {
                    int rot = ((s >> 2) & 3) << 1;
                    const float* hb = sc + SC_H + s * 32;
                    float4 h0 = *(const float4*)(hb + (((2 * hh + rot) & 7) << 2));
                    float4 h1 = *(const float4*)(hb + (((2 * hh + 1 + rot) & 7) << 2));
                    float ak = bkr, av = bvr;
                    ak = fmaf(h0.x, wkr[0], ak); av = fmaf(h0.x, wvr[0], av);
                    ak = fmaf(h0.y, wkr[1], ak); av = fmaf(h0.y, wvr[1], av);
                    ak = fmaf(h0.z, wkr[2], ak); av = fmaf(h0.z, wvr[2], av);
                    ak = fmaf(h0.w, wkr[3], ak); av = fmaf(h0.w, wvr[3], av);
                    ak = fmaf(h1.x, wkr[4], ak); av = fmaf(h1.x, wvr[4], av);
                    ak = fmaf(h1.y, wkr[5], ak); av = fmaf(h1.y, wvr[5], av);
                    ak = fmaf(h1.z, wkr[6], ak); av = fmaf(h1.z, wvr[6], av);
                    ak = fmaf(h1.w, wkr[7], ak); av = fmaf(h1.w, wvr[7], av);
                    float t2 = q0 * ak;
                    t2 += __shfl_xor_sync(0xffffffffu, t2, 1);
                    t2 += __shfl_xor_sync(0xffffffffu, t2, 2);
                    t2 += __shfl_xor_sync(0xffffffffu, t2, 4);
                    float p = __expf(t2);   // scores ~N(0,1): no max shift needed
                    ssum += p;
                    oacc = fmaf(p, av, oacc);
                }
                oe = oacc * __frcp_rn(ssum);
            }
            sc[SC_ROW + lane] = oe;
            __syncwarp();

            // ---- output projection + residual -> mh; LN2 -> h2 batch ----
            {
                const float* WoS = sm + OFF_WO + hh * 72 + ee;
                float4 o0 = *(const float4*)(sc + SC_ROW + hh * 8);
                float4 o1 = *(const float4*)(sc + SC_ROW + hh * 8 + 4);
                float a = sm[OFF_BO + lane];
                a = fmaf(o0.x, WoS[0],  a); a = fmaf(o0.y, WoS[8],  a);
                a = fmaf(o0.z, WoS[16], a); a = fmaf(o0.w, WoS[24], a);
                a = fmaf(o1.x, WoS[32], a); a = fmaf(o1.y, WoS[40], a);
                a = fmaf(o1.z, WoS[48], a); a = fmaf(o1.w, WoS[56], a);
                float mh = a + sc[SC_X0 + lane];
                mh_arr[it] = mh;
                float h2 = warp_ln32(mh, gg, bb);
                sc[SC_H2B + it * 32 + lane] = h2;
            }
            __syncwarp();
        }

        // ============ batched row phases (2 images at once) ============

        // ---- y1[it] = relu(h2[it] @ W1 + b1) ----
        {
            const float* w1t = sm + OFF_W1T + lane * 36;
            float a[IMGS];
            float b1r = sm[OFF_B1 + lane];
            #pragma unroll
            for (int t = 0; t < IMGS; t++) a[t] = b1r;
            #pragma unroll
            for (int d4 = 0; d4 < 8; d4++) {
                float4 wv = *(const float4*)(w1t + d4 * 4);
                #pragma unroll
                for (int t = 0; t < IMGS; t++) {
                    float4 hv = *(const float4*)(sc + SC_H2B + t * 32 + d4 * 4);
                    a[t] = fmaf(hv.x, wv.x, a[t]); a[t] = fmaf(hv.y, wv.y, a[t]);
                    a[t] = fmaf(hv.z, wv.z, a[t]); a[t] = fmaf(hv.w, wv.w, a[t]);
                }
            }
            __syncwarp();   // PIX region fully dead now
            #pragma unroll
            for (int t = 0; t < IMGS; t++) sc[SC_Y1 + t * 32 + lane] = fmaxf(a[t], 0.0f);
        }
        __syncwarp();

        // ---- enc[it] = mh[it] + y1[it] @ W2 + b2 ----
        {
            const float* w2t = sm + OFF_W2T + lane * 36;
            float a[IMGS];
            float b2r = sm[OFF_B2 + lane];
            #pragma unroll
            for (int t = 0; t < IMGS; t++) a[t] = b2r;
            #pragma unroll
            for (int d4 = 0; d4 < 8; d4++) {
                float4 wv = *(const float4*)(w2t + d4 * 4);
                #pragma unroll
                for (int t = 0; t < IMGS; t++) {
                    float4 hv = *(const float4*)(sc + SC_Y1 + t * 32 + d4 * 4);
                    a[t] = fmaf(hv.x, wv.x, a[t]); a[t] = fmaf(hv.y, wv.y, a[t]);
                    a[t] = fmaf(hv.z, wv.z, a[t]); a[t] = fmaf(hv.w, wv.w, a[t]);
                }
            }
            #pragma unroll
            for (int t = 0; t < IMGS; t++) sc[SC_ENC + t * 32 + lane] = mh_arr[t] + a[t];
        }
        __syncwarp();

        // ---- c1[it] = relu(enc[it] @ Wc1 + bc1) ----
        {
            const float* wa = sm + OFF_WC1T + lane * 36;
            const float* wb = sm + OFF_WC1T + (lane + 32) * 36;
            float a0[IMGS], a1[IMGS];
            float bc1a = sm[OFF_BC1 + lane], bc1b = sm[OFF_BC1 + 32 + lane];
            #pragma unroll
            for (int t = 0; t < IMGS; t++) { a0[t] = bc1a; a1[t] = bc1b; }
            #pragma unroll
            for (int d4 = 0; d4 < 8; d4++) {
                float4 va = *(const float4*)(wa + d4 * 4);
                float4 vb = *(const float4*)(wb + d4 * 4);
                #pragma unroll
                for (int t = 0; t < IMGS; t++) {
                    float4 ev = *(const float4*)(sc + SC_ENC + t * 32 + d4 * 4);
                    a0[t] = fmaf(ev.x, va.x, a0[t]); a1[t] = fmaf(ev.x, vb.x, a1[t]);
                    a0[t] = fmaf(ev.y, va.y, a0[t]); a1[t] = fmaf(ev.y, vb.y, a1[t]);
                    a0[t] = fmaf(ev.z, va.z, a0[t]); a1[t] = fmaf(ev.z, vb.z, a1[t]);
                    a0[t] = fmaf(ev.w, va.w, a0[t]); a1[t] = fmaf(ev.w, vb.w, a1[t]);
                }
            }
            #pragma unroll
            for (int t = 0; t < IMGS; t++) {
                sc[SC_C1B + t * 64 + lane]      = fmaxf(a0[t], 0.0f);
                sc[SC_C1B + t * 64 + 32 + lane] = fmaxf(a1[t], 0.0f);
            }
        }
        __syncwarp();

        // ---- c2: 10 logits per image; both images in one pass ----
        {
            int im = lane >> 4;
            int l  = lane & 15;
            if (l < 10) {
                const float* w = sm + OFF_WC2T + l * 68;
                const float* c1v = sc + SC_C1B + im * 64;
                float a = sm[OFF_BC2 + l];
                #pragma unroll
                for (int m4 = 0; m4 < 16; m4++) {
                    float4 cv = *(const float4*)(c1v + m4 * 4);
                    float4 wv = *(const float4*)(w + m4 * 4);
                    a = fmaf(cv.x, wv.x, a); a = fmaf(cv.y, wv.y, a);
                    a = fmaf(cv.z, wv.z, a); a = fmaf(cv.w, wv.w, a);
                }
                out[(imgBase + im) * 10 + l] = a;
            }
        }
        __syncwarp();   // C1B (inside PIX region) fully consumed before next iteration
    }
}

extern "C" void kernel_launch(void* const* d_in, const int* in_sizes, int n_in,
                              void* d_out, int out_size) {
    (void)in_sizes; (void)n_in; (void)out_size;
    const float* img   = (const float*)d_in[0];
    const float* W_map = (const float*)d_in[1];
    const float* b_map = (const float*)d_in[2];
    const float* ln_g  = (const float*)d_in[3];
    const float* ln_b  = (const float*)d_in[4];
    const float* Wq    = (const float*)d_in[5];
    const float* bq    = (const float*)d_in[6];
    const float* Wk    = (const float*)d_in[7];
    const float* bk    = (const float*)d_in[8];
    const float* Wv    = (const float*)d_in[9];
    const float* bv    = (const float*)d_in[10];
    const float* Wo    = (const float*)d_in[11];
    const float* bo    = (const float*)d_in[12];
    const float* W1    = (const float*)d_in[13];
    const float* b1    = (const float*)d_in[14];
    const float* W2    = (const float*)d_in[15];
    const float* b2    = (const float*)d_in[16];
    const float* Wc1   = (const float*)d_in[17];
    const float* bc1   = (const float*)d_in[18];
    const float* Wc2   = (const float*)d_in[19];
    const float* bc2   = (const float*)d_in[20];
    float* out = (float*)d_out;

    cudaFuncSetAttribute(vit_kernel, cudaFuncAttributeMaxDynamicSharedMemorySize, SMEM_BYTES);
    vit_kernel<<<GRIDB, NTHREADS, SMEM_BYTES>>>(
        img, W_map, b_map, ln_g, ln_b, Wq, bq, Wk, bk, Wv, bv, Wo, bo,
        W1, b1, W2, b2, Wc1, bc1, Wc2, bc2, out);
}

// round 15
// speedup vs baseline: 1.0123x; 1.0123x over previous
#include <cuda_runtime.h>

#define NBATCH   32768
#define WARPS    8
#define NTHREADS 256
#define IMGS     2
#define GRIDB    444                     // 148 SMs x 3 resident blocks
#define NGROUPS  (NBATCH / IMGS)         // 16384
#define WSTRIDE  (GRIDB * WARPS)         // 3552 warps

// ---- weight region offsets (floats) ----
#define OFF_WT   0        // patch-embed weights, cc-major k: WT[c][k'] stride 52, k'=cc*7+rr, pad 49..51
#define OFF_BMAP 1440
#define OFF_LNG  1464
#define OFF_LNB  1496
#define OFF_WQ   1528     // 4 heads x 72
#define OFF_WK   1816
#define OFF_WV   2104
#define OFF_WO   2392
#define OFF_BQ   2680
#define OFF_BK   2712
#define OFF_BV   2744
#define OFF_BO   2776
#define OFF_W1T  2808     // W1 transposed: 32 x 36
#define OFF_B1   3960
#define OFF_W2T  3992     // 32 x 36
#define OFF_B2   5144
#define OFF_WC1T 5176     // 64 x 36
#define OFF_BC1  7480
#define OFF_WC2T 7544     // 10 x 68
#define OFF_BC2  8224
#define WEIGHT_FLOATS 8240

// ---- per-warp scratch (floats) ----
#define SC_PIX 0          // 856 floats; dead after phase B
#define SC_H   0          // 16 x 32 quad-rotated (overlays PIX, [0,512))
#define SC_Y1  0          // 2 x 32 (row phases reuse dead PIX)
#define SC_ENC 64         // 2 x 32
#define SC_C1B 128        // 2 x 64
#define SC_ROW 960        // 32: oe scratch
#define SC_X0  992        // 32
#define SC_H2B 1024       // 2 x 32 batched h2 (must NOT overlap PIX)
#define SCRATCH_PER_WARP 1088

#define SMEM_FLOATS (WEIGHT_FLOATS + WARPS * SCRATCH_PER_WARP)   // 16944
#define SMEM_BYTES  (SMEM_FLOATS * 4)                            // 67776 B -> 3 blocks/SM

typedef unsigned long long ull;

__device__ __forceinline__ ull pk2(float lo, float hi) {
    ull r; asm("mov.b64 %0, {%1, %2};" : "=l"(r) : "f"(lo), "f"(hi)); return r;
}
__device__ __forceinline__ void up2(float& lo, float& hi, ull v) {
    asm("mov.b64 {%0, %1}, %2;" : "=f"(lo), "=f"(hi) : "l"(v));
}
__device__ __forceinline__ void ffma2(ull& acc, ull a, ull b) {
    asm("fma.rn.f32x2 %0, %1, %2, %0;" : "+l"(acc) : "l"(a), "l"(b));
}

__device__ __forceinline__ float warp_ln32(float v, float gg, float bb) {
    float s1 = v, s2 = v * v;
    #pragma unroll
    for (int o = 16; o; o >>= 1) {
        s1 += __shfl_xor_sync(0xffffffffu, s1, o);
        s2 += __shfl_xor_sync(0xffffffffu, s2, o);
    }
    float mu  = s1 * 0.03125f;
    float var = fmaf(s2, 0.03125f, -mu * mu);
    float rstd = rsqrtf(var + 1e-5f);
    return (v - mu) * rstd * gg + bb;
}

// h layout: h[t][c] at t*32 + (((c>>2) + 2*(t>>2)) & 7)*4 + (c&3)
__device__ __forceinline__ int haddr(int t, int c) {
    return t * 32 + (((((c >> 2) + ((t >> 2) << 1)) & 7)) << 2) + (c & 3);
}

__global__ __launch_bounds__(NTHREADS, 3)
void vit_kernel(const float* __restrict__ img,
                const float* __restrict__ W_map, const float* __restrict__ b_map,
                const float* __restrict__ ln_g,  const float* __restrict__ ln_b,
                const float* __restrict__ Wq, const float* __restrict__ bq,
                const float* __restrict__ Wk, const float* __restrict__ bk,
                const float* __restrict__ Wv, const float* __restrict__ bv,
                const float* __restrict__ Wo, const float* __restrict__ bo,
                const float* __restrict__ W1, const float* __restrict__ b1,
                const float* __restrict__ W2, const float* __restrict__ b2,
                const float* __restrict__ Wc1, const float* __restrict__ bc1,
                const float* __restrict__ Wc2, const float* __restrict__ bc2,
                float* __restrict__ out)
{
    extern __shared__ float sm[];
    const int tid = threadIdx.x;

    // ---- cooperative weight staging: ONCE per block ----
    for (int i = tid; i < 1248; i += NTHREADS) {
        int c = i / 52, k = i - c * 52;
        float v = 0.0f;
        if (k < 49) {
            int cc = k / 7, rr = k - cc * 7;
            v = W_map[(rr * 7 + cc) * 24 + c];
        }
        sm[OFF_WT + i] = v;
    }
    for (int i = tid; i < 24; i += NTHREADS) sm[OFF_BMAP + i] = b_map[i];
    for (int i = tid; i < 32; i += NTHREADS) {
        sm[OFF_LNG + i] = ln_g[i]; sm[OFF_LNB + i] = ln_b[i];
        sm[OFF_BQ  + i] = bq[i];   sm[OFF_BK  + i] = bk[i];
        sm[OFF_BV  + i] = bv[i];   sm[OFF_BO  + i] = bo[i];
        sm[OFF_B1  + i] = b1[i];   sm[OFF_B2  + i] = b2[i];
    }
    for (int i = tid; i < 256; i += NTHREADS) {
        int h = i >> 6, r = i & 63;
        sm[OFF_WQ + h * 72 + r] = Wq[i];
        sm[OFF_WK + h * 72 + r] = Wk[i];
        sm[OFF_WV + h * 72 + r] = Wv[i];
        sm[OFF_WO + h * 72 + r] = Wo[i];
    }
    for (int i = tid; i < 1152; i += NTHREADS) {
        int col = i / 36, d = i - col * 36;
        sm[OFF_W1T + i] = (d < 32) ? W1[d * 32 + col] : 0.0f;
        sm[OFF_W2T + i] = (d < 32) ? W2[d * 32 + col] : 0.0f;
    }
    for (int i = tid; i < 2304; i += NTHREADS) {
        int o = i / 36, d = i - o * 36;
        sm[OFF_WC1T + i] = (d < 32) ? Wc1[d * 64 + o] : 0.0f;
    }
    for (int i = tid; i < 64; i += NTHREADS) sm[OFF_BC1 + i] = bc1[i];
    for (int i = tid; i < 680; i += NTHREADS) {
        int o = i / 68, m = i - o * 68;
        sm[OFF_WC2T + i] = (m < 64) ? Wc2[m * 10 + o] : 0.0f;
    }
    for (int i = tid; i < 16; i += NTHREADS) sm[OFF_BC2 + i] = (i < 10) ? bc2[i] : 0.0f;
    __syncthreads();

    const int warp = tid >> 5, lane = tid & 31;
    float* sc = sm + WEIGHT_FLOATS + warp * SCRATCH_PER_WARP;
    const int grp = lane >> 3, colgrp = lane & 7;
    const int hh = lane >> 3, ee = lane & 7;
    const int gwarp = blockIdx.x * WARPS + warp;

    // ---- block-lifetime register-resident constants ----
    const float gg = sm[OFF_LNG + lane], bb = sm[OFF_LNB + lane];
    float wkr[8], wvr[8];
    {
        const float* WkS = sm + OFF_WK + hh * 72 + ee;
        const float* WvS = sm + OFF_WV + hh * 72 + ee;
        #pragma unroll
        for (int e = 0; e < 8; e++) { wkr[e] = WkS[e * 8]; wvr[e] = WvS[e * 8]; }
    }
    const float bkr = sm[OFF_BK + lane], bvr = sm[OFF_BV + lane];
    const float bqr = sm[OFF_BQ + lane];

    // ---- one-time zeroing of persistent PIX pads (region >= 512, never overwritten by H) ----
    {
        int idx = lane + 24;   // pads for t = 8..15 live at offsets >= 512
        if (idx < 48) {
            int t = idx / 3, kp = 49 + idx - (idx / 3) * 3;
            sc[SC_PIX + (t >> 2) * 216 + kp * 4 + (t & 3)] = 0.0f;
        }
    }
    __syncwarp();

    // ---- persistent warp loop over image pairs ----
    #pragma unroll 1
    for (int g = gwarp; g < NGROUPS; g += WSTRIDE) {
        const int imgBase = g * IMGS;
        float mh_arr[IMGS];

        #pragma unroll 1
        for (int it = 0; it < IMGS; ++it) {
            const int imgIdx = imgBase + it;

            // ---- Phase A: load image -> token-minor pixel layout ----
            {
                const float4* gim4 = (const float4*)(img + (size_t)imgIdx * 784);
                #pragma unroll
                for (int k2 = 0; k2 < 7; k2++) {
                    int i4 = lane + k2 * 32;
                    if (i4 < 196) {
                        float4 v = gim4[i4];
                        float vals[4] = {v.x, v.y, v.z, v.w};
                        int p0 = i4 * 4;
                        #pragma unroll
                        for (int b = 0; b < 4; b++) {
                            int p = p0 + b;
                            int row = p / 28, col = p - row * 28;
                            int pr = row / 7, rr = row - pr * 7;
                            int pc = col / 7, cc = col - pc * 7;
                            sc[SC_PIX + pr * 216 + (cc * 7 + rr) * 4 + pc] = vals[b];
                        }
                    }
                }
                // re-zero only pads inside [0,512) (overwritten by H each iteration)
                if (lane < 24) {
                    int t = lane / 3, kp = 49 + lane - (lane / 3) * 3;
                    sc[SC_PIX + (t >> 2) * 216 + kp * 4 + (t & 3)] = 0.0f;
                }
            }
            __syncwarp();

            // ---- Phase B: patch embedding, packed f32x2 ----
            float acc[4][3];
            {
                const float* pixbase = sc + SC_PIX + grp * 216;
                const float* wt = sm + OFF_WT + colgrp * 156;
                ull accp[3][2];
                #pragma unroll
                for (int c = 0; c < 3; c++) {
                    float bm = sm[OFF_BMAP + colgrp * 3 + c];
                    accp[c][0] = pk2(bm, bm);
                    accp[c][1] = accp[c][0];
                }
                #pragma unroll
                for (int k4 = 0; k4 < 13; k4++) {
                    ulonglong2 pv0 = *(const ulonglong2*)(pixbase + (k4 * 4 + 0) * 4);
                    ulonglong2 pv1 = *(const ulonglong2*)(pixbase + (k4 * 4 + 1) * 4);
                    ulonglong2 pv2 = *(const ulonglong2*)(pixbase + (k4 * 4 + 2) * 4);
                    ulonglong2 pv3 = *(const ulonglong2*)(pixbase + (k4 * 4 + 3) * 4);
                    #pragma unroll
                    for (int c = 0; c < 3; c++) {
                        float4 w = *(const float4*)(wt + c * 52 + k4 * 4);
                        ull w0 = pk2(w.x, w.x), w1 = pk2(w.y, w.y);
                        ull w2 = pk2(w.z, w.z), w3 = pk2(w.w, w.w);
                        ffma2(accp[c][0], pv0.x, w0); ffma2(accp[c][1], pv0.y, w0);
                        ffma2(accp[c][0], pv1.x, w1); ffma2(accp[c][1], pv1.y, w1);
                        ffma2(accp[c][0], pv2.x, w2); ffma2(accp[c][1], pv2.y, w2);
                        ffma2(accp[c][0], pv3.x, w3); ffma2(accp[c][1], pv3.y, w3);
                    }
                }
                #pragma unroll
                for (int c = 0; c < 3; c++) {
                    up2(acc[0][c], acc[1][c], accp[c][0]);
                    up2(acc[2][c], acc[3][c], accp[c][1]);
                }
            }
            __syncwarp();     // everyone done reading PIX before H overlays it

            // ---- Phase C: LayerNorm 1 on register tile; H overlays PIX ----
            {
                const int c0 = 8 + colgrp * 3;
                const float g0 = sm[OFF_LNG + c0],     b0 = sm[OFF_LNB + c0];
                const float g1 = sm[OFF_LNG + c0 + 1], b1v = sm[OFF_LNB + c0 + 1];
                const float g2 = sm[OFF_LNG + c0 + 2], b2v = sm[OFF_LNB + c0 + 2];
                const float gp = sm[OFF_LNG + colgrp], bp = sm[OFF_LNB + colgrp];
                #pragma unroll
                for (int j = 0; j < 4; j++) {
                    float a0 = acc[j][0], a1 = acc[j][1], a2 = acc[j][2];
                    float s1 = a0 + a1 + a2;
                    float s2 = fmaf(a0, a0, fmaf(a1, a1, a2 * a2));
                    #pragma unroll
                    for (int o = 1; o < 8; o <<= 1) {
                        s1 += __shfl_xor_sync(0xffffffffu, s1, o);
                        s2 += __shfl_xor_sync(0xffffffffu, s2, o);
                    }
                    float mu = s1 * 0.03125f;
                    float var = fmaf(s2, 0.03125f, -mu * mu);
                    float rstd = rsqrtf(var + 1e-5f);
                    int t = grp * 4 + j;
                    sc[SC_H + haddr(t, colgrp)] = fmaf(-mu * rstd, gp, bp);
                    sc[SC_H + haddr(t, c0    )] = fmaf((a0 - mu) * rstd, g0, b0);
                    sc[SC_H + haddr(t, c0 + 1)] = fmaf((a1 - mu) * rstd, g1, b1v);
                    sc[SC_H + haddr(t, c0 + 2)] = fmaf((a2 - mu) * rstd, g2, b2v);
                }
                if (grp == 0) {
                    sc[SC_X0 + c0] = acc[0][0]; sc[SC_X0 + c0 + 1] = acc[0][1]; sc[SC_X0 + c0 + 2] = acc[0][2];
                }
                if (lane < 8) sc[SC_X0 + lane] = 0.0f;
            }
            __syncwarp();

            // ---- Phase D+E fused: q0 peel, then online-softmax attention (exp2 form) ----
            float oe;
            {
                float q0;
                {
                    const float* WqS = sm + OFF_WQ + hh * 72 + ee;
                    const float* hb = sc + SC_H;
                    float4 h0 = *(const float4*)(hb + (((2 * hh) & 7) << 2));
                    float4 h1 = *(const float4*)(hb + (((2 * hh + 1) & 7) << 2));
                    float aq = bqr;
                    aq = fmaf(h0.x, WqS[0],  aq); aq = fmaf(h0.y, WqS[8],  aq);
                    aq = fmaf(h0.z, WqS[16], aq); aq = fmaf(h0.w, WqS[24], aq);
                    aq = fmaf(h1.x, WqS[32], aq); aq = fmaf(h1.y, WqS[40], aq);
                    aq = fmaf(h1.z, WqS[48], aq); aq = fmaf(h1.w, WqS[56], aq);
                    q0 = aq * 0.51006967f;   // (1/sqrt(8)) * log2(e) folded into q
                }
                float ssum = 0.0f, oacc = 0.0f;
                #pragma unroll
                for (int s = 0; s < 16; s++) {
                    int rot = ((s >> 2) & 3) << 1;
                    const float* hb = sc + SC_H + s * 32;
                    float4 h0 = *(const float4*)(hb + (((2 * hh + rot) & 7) << 2));
                    float4 h1 = *(const float4*)(hb + (((2 * hh + 1 + rot) & 7) << 2));
                    float ak = bkr, av = bvr;
                    ak = fmaf(h0.x, wkr[0], ak); av = fmaf(h0.x, wvr[0], av);
                    ak = fmaf(h0.y, wkr[1], ak); av = fmaf(h0.y, wvr[1], av);
                    ak = fmaf(h0.z, wkr[2], ak); av = fmaf(h0.z, wvr[2], av);
                    ak = fmaf(h0.w, wkr[3], ak); av = fmaf(h0.w, wvr[3], av);
                    ak = fmaf(h1.x, wkr[4], ak); av = fmaf(h1.x, wvr[4], av);
                    ak = fmaf(h1.y, wkr[5], ak); av = fmaf(h1.y, wvr[5], av);
                    ak = fmaf(h1.z, wkr[6], ak); av = fmaf(h1.z, wvr[6], av);
                    ak = fmaf(h1.w, wkr[7], ak); av = fmaf(h1.w, wvr[7], av);
                    float t2 = q0 * ak;
                    t2 += __shfl_xor_sync(0xffffffffu, t2, 1);
                    t2 += __shfl_xor_sync(0xffffffffu, t2, 2);
                    t2 += __shfl_xor_sync(0xffffffffu, t2, 4);
                    float p = exp2f(t2);   // scores ~N(0,1): no max shift needed
                    ssum += p;
                    oacc = fmaf(p, av, oacc);
                }
                oe = oacc * __frcp_rn(ssum);
            }
            sc[SC_ROW + lane] = oe;
            __syncwarp();

            // ---- output projection + residual -> mh; LN2 -> h2 batch ----
            {
                const float* WoS = sm + OFF_WO + hh * 72 + ee;
                float4 o0 = *(const float4*)(sc + SC_ROW + hh * 8);
                float4 o1 = *(const float4*)(sc + SC_ROW + hh * 8 + 4);
                float a = sm[OFF_BO + lane];
                a = fmaf(o0.x, WoS[0],  a); a = fmaf(o0.y, WoS[8],  a);
                a = fmaf(o0.z, WoS[16], a); a = fmaf(o0.w, WoS[24], a);
                a = fmaf(o1.x, WoS[32], a); a = fmaf(o1.y, WoS[40], a);
                a = fmaf(o1.z, WoS[48], a); a = fmaf(o1.w, WoS[56], a);
                float mh = a + sc[SC_X0 + lane];
                mh_arr[it] = mh;
                float h2 = warp_ln32(mh, gg, bb);
                sc[SC_H2B + it * 32 + lane] = h2;
            }
            __syncwarp();
        }

        // ============ batched row phases (2 images at once) ============

        // ---- y1[it] = relu(h2[it] @ W1 + b1) ----
        {
            const float* w1t = sm + OFF_W1T + lane * 36;
            float a[IMGS];
            float b1r = sm[OFF_B1 + lane];
            #pragma unroll
            for (int t = 0; t < IMGS; t++) a[t] = b1r;
            #pragma unroll
            for (int d4 = 0; d4 < 8; d4++) {
                float4 wv = *(const float4*)(w1t + d4 * 4);
                #pragma unroll
                for (int t = 0; t < IMGS; t++) {
                    float4 hv = *(const float4*)(sc + SC_H2B + t * 32 + d4 * 4);
                    a[t] = fmaf(hv.x, wv.x, a[t]); a[t] = fmaf(hv.y, wv.y, a[t]);
                    a[t] = fmaf(hv.z, wv.z, a[t]); a[t] = fmaf(hv.w, wv.w, a[t]);
                }
            }
            __syncwarp();   // PIX region fully dead now
            #pragma unroll
            for (int t = 0; t < IMGS; t++) sc[SC_Y1 + t * 32 + lane] = fmaxf(a[t], 0.0f);
        }
        __syncwarp();

        // ---- enc[it] = mh[it] + y1[it] @ W2 + b2 ----
        {
            const float* w2t = sm + OFF_W2T + lane * 36;
            float a[IMGS];
            float b2r = sm[OFF_B2 + lane];
            #pragma unroll
            for (int t = 0; t < IMGS; t++) a[t] = b2r;
            #pragma unroll
            for (int d4 = 0; d4 < 8; d4++) {
                float4 wv = *(const float4*)(w2t + d4 * 4);
                #pragma unroll
                for (int t = 0; t < IMGS; t++) {
                    float4 hv = *(const float4*)(sc + SC_Y1 + t * 32 + d4 * 4);
                    a[t] = fmaf(hv.x, wv.x, a[t]); a[t] = fmaf(hv.y, wv.y, a[t]);
                    a[t] = fmaf(hv.z, wv.z, a[t]); a[t] = fmaf(hv.w, wv.w, a[t]);
                }
            }
            #pragma unroll
            for (int t = 0; t < IMGS; t++) sc[SC_ENC + t * 32 + lane] = mh_arr[t] + a[t];
        }
        __syncwarp();

        // ---- c1[it] = relu(enc[it] @ Wc1 + bc1) ----
        {
            const float* wa = sm + OFF_WC1T + lane * 36;
            const float* wb = sm + OFF_WC1T + (lane + 32) * 36;
            float a0[IMGS], a1[IMGS];
            float bc1a = sm[OFF_BC1 + lane], bc1b = sm[OFF_BC1 + 32 + lane];
            #pragma unroll
            for (int t = 0; t < IMGS; t++) { a0[t] = bc1a; a1[t] = bc1b; }
            #pragma unroll
            for (int d4 = 0; d4 < 8; d4++) {
                float4 va = *(const float4*)(wa + d4 * 4);
                float4 vb = *(const float4*)(wb + d4 * 4);
                #pragma unroll
                for (int t = 0; t < IMGS; t++) {
                    float4 ev = *(const float4*)(sc + SC_ENC + t * 32 + d4 * 4);
                    a0[t] = fmaf(ev.x, va.x, a0[t]); a1[t] = fmaf(ev.x, vb.x, a1[t]);
                    a0[t] = fmaf(ev.y, va.y, a0[t]); a1[t] = fmaf(ev.y, vb.y, a1[t]);
                    a0[t] = fmaf(ev.z, va.z, a0[t]); a1[t] = fmaf(ev.z, vb.z, a1[t]);
                    a0[t] = fmaf(ev.w, va.w, a0[t]); a1[t] = fmaf(ev.w, vb.w, a1[t]);
                }
            }
            #pragma unroll
            for (int t = 0; t < IMGS; t++) {
                sc[SC_C1B + t * 64 + lane]      = fmaxf(a0[t], 0.0f);
                sc[SC_C1B + t * 64 + 32 + lane] = fmaxf(a1[t], 0.0f);
            }
        }
        __syncwarp();

        // ---- c2: 10 logits per image; both images in one pass ----
        {
            int im = lane >> 4;
            int l  = lane & 15;
            if (l < 10) {
                const float* w = sm + OFF_WC2T + l * 68;
                const float* c1v = sc + SC_C1B + im * 64;
                float a = sm[OFF_BC2 + l];
                #pragma unroll
                for (int m4 = 0; m4 < 16; m4++) {
                    float4 cv = *(const float4*)(c1v + m4 * 4);
                    float4 wv = *(const float4*)(w + m4 * 4);
                    a = fmaf(cv.x, wv.x, a); a = fmaf(cv.y, wv.y, a);
                    a = fmaf(cv.z, wv.z, a); a = fmaf(cv.w, wv.w, a);
                }
                out[(imgBase + im) * 10 + l] = a;
            }
        }
        __syncwarp();   // C1B (inside PIX region) fully consumed before next iteration
    }
}

extern "C" void kernel_launch(void* const* d_in, const int* in_sizes, int n_in,
                              void* d_out, int out_size) {
    (void)in_sizes; (void)n_in; (void)out_size;
    const float* img   = (const float*)d_in[0];
    const float* W_map = (const float*)d_in[1];
    const float* b_map = (const float*)d_in[2];
    const float* ln_g  = (const float*)d_in[3];
    const float* ln_b  = (const float*)d_in[4];
    const float* Wq    = (const float*)d_in[5];
    const float* bq    = (const float*)d_in[6];
    const float* Wk    = (const float*)d_in[7];
    const float* bk    = (const float*)d_in[8];
    const float* Wv    = (const float*)d_in[9];
    const float* bv    = (const float*)d_in[10];
    const float* Wo    = (const float*)d_in[11];
    const float* bo    = (const float*)d_in[12];
    const float* W1    = (const float*)d_in[13];
    const float* b1    = (const float*)d_in[14];
    const float* W2    = (const float*)d_in[15];
    const float* b2    = (const float*)d_in[16];
    const float* Wc1   = (const float*)d_in[17];
    const float* bc1   = (const float*)d_in[18];
    const float* Wc2   = (const float*)d_in[19];
    const float* bc2   = (const float*)d_in[20];
    float* out = (float*)d_out;

    cudaFuncSetAttribute(vit_kernel, cudaFuncAttributeMaxDynamicSharedMemorySize, SMEM_BYTES);
    vit_kernel<<<GRIDB, NTHREADS, SMEM_BYTES>>>(
        img, W_map, b_map, ln_g, ln_b, Wq, bq, Wk, bk, Wv, bv, Wo, bo,
        W1, b1, W2, b2, Wc1, bc1, Wc2, bc2, out);
}